// round 16
// baseline (speedup 1.0000x reference)
#include <cuda_runtime.h>
#include <cuda_fp16.h>
#include <math.h>
#include <stdint.h>

#define BATCH 16
#define CCH   256
#define HW    4096
#define NPOS  (BATCH*HW)
#define QDIM  64
#define SD    512
#define NANG  18

typedef unsigned short ushort_t;

// ---------------- scratch globals ----------------
__device__ float g_Uri[BATCH * 8192];            // rows 2a=Re, 2a+1=Im of U
__device__ float g_bf[BATCH * 128];              // Ũ @ b1
__device__ __align__(16) ushort_t g_A1h[BATCH][32768];
__device__ __align__(16) ushort_t g_A1l[BATCH][32768];
__device__ __align__(16) ushort_t g_A2h[16384];
__device__ __align__(16) ushort_t g_A2l[16384];

// ---------------- mma helper ----------------
__device__ __forceinline__ void mma16816(float* c, uint32_t a0, uint32_t a1,
                                         uint32_t a2, uint32_t a3,
                                         uint32_t b0, uint32_t b1) {
  asm volatile(
      "mma.sync.aligned.m16n8k16.row.col.f32.f16.f16.f32 "
      "{%0,%1,%2,%3}, {%4,%5,%6,%7}, {%8,%9}, {%0,%1,%2,%3};"
      : "+f"(c[0]), "+f"(c[1]), "+f"(c[2]), "+f"(c[3])
      : "r"(a0), "r"(a1), "r"(a2), "r"(a3), "r"(b0), "r"(b1));
}

__device__ __forceinline__ void split16(float v, ushort_t& h, ushort_t& l) {
  __half hh = __float2half_rn(v);
  float lo = v - __half2float(hh);
  h = __half_as_ushort(hh);
  l = __half_as_ushort(__float2half_rn(lo));
}

// fragment-linear ushort index for A operand (m16n8k16 row-major A)
__device__ __forceinline__ int frag_idx(int r, int k, int KS) {
  int mt = r >> 4, rr = r & 15;
  int gID = rr & 7, sm = rr >> 3;
  int ks = k >> 4, kin = k & 15;
  int sk = kin >> 3, tg = (kin & 7) >> 1, hf = kin & 1;
  return (((mt * KS + ks) * 32 + gID * 4 + tg) * 4 + (sm + 2 * sk)) * 2 + hf;
}

// ---------------- circuit helpers ----------------
__device__ __forceinline__ void rx_sh(float& r0, float& i0, float& r1, float& i1,
                                      float c, float s, int L) {
  float pr0 = __shfl_xor_sync(0xffffffffu, r0, L), pi0 = __shfl_xor_sync(0xffffffffu, i0, L);
  float pr1 = __shfl_xor_sync(0xffffffffu, r1, L), pi1 = __shfl_xor_sync(0xffffffffu, i1, L);
  r0 = fmaf(s, pi0, c * r0);  i0 = fmaf(-s, pr0, c * i0);
  r1 = fmaf(s, pi1, c * r1);  i1 = fmaf(-s, pr1, c * i1);
}
__device__ __forceinline__ void rx_loc(float& r0, float& i0, float& r1, float& i1,
                                       float c, float s) {
  float nr0 = fmaf(s, i1, c * r0), ni0 = fmaf(-s, r1, c * i0);
  float nr1 = fmaf(s, i0, c * r1), ni1 = fmaf(-s, r0, c * i1);
  r0 = nr0; i0 = ni0; r1 = nr1; i1 = ni1;
}
__device__ __forceinline__ void ry_sh(float& r0, float& i0, float& r1, float& i1,
                                      float c, float s, int L, int lane) {
  float t = (lane & L) ? s : -s;
  float pr0 = __shfl_xor_sync(0xffffffffu, r0, L), pi0 = __shfl_xor_sync(0xffffffffu, i0, L);
  float pr1 = __shfl_xor_sync(0xffffffffu, r1, L), pi1 = __shfl_xor_sync(0xffffffffu, i1, L);
  r0 = fmaf(t, pr0, c * r0);  i0 = fmaf(t, pi0, c * i0);
  r1 = fmaf(t, pr1, c * r1);  i1 = fmaf(t, pi1, c * i1);
}
__device__ __forceinline__ void ry_loc(float& r0, float& i0, float& r1, float& i1,
                                       float c, float s) {
  float nr0 = fmaf(-s, r1, c * r0), ni0 = fmaf(-s, i1, c * i0);
  float nr1 = fmaf(s, r0, c * r1),  ni1 = fmaf(s, i0, c * i1);
  r0 = nr0; i0 = ni0; r1 = nr1; i1 = ni1;
}

// ---------------------------------------------------------------------------
// Kernel 1: angles + build U + bias fold (16 blocks, one per batch)
// ---------------------------------------------------------------------------
__global__ __launch_bounds__(256) void k_u(
    const float* __restrict__ style, const float* __restrict__ smw,
    const float* __restrict__ smb, const float* __restrict__ wts,
    const float* __restrict__ b1) {
  __shared__ float Us[8192];
  __shared__ float cth[NANG], sth[NANG];
  int b = blockIdx.x, tid = threadIdx.x;
  int w = tid >> 5, lane = tid & 31;

  for (int o = w; o < NANG; o += 8) {
    float p = 0.f;
#pragma unroll
    for (int j = 0; j < 16; j++)
      p += smw[o * SD + lane + 32 * j] * style[b * SD + lane + 32 * j];
#pragma unroll
    for (int off = 16; off > 0; off >>= 1) p += __shfl_xor_sync(0xffffffffu, p, off);
    if (lane == 0) {
      float tp = wts[o] + smb[o] + p;
      cth[o] = cosf(0.5f * tp);
      sth[o] = sinf(0.5f * tp);
    }
  }
  __syncthreads();

  for (int t = 0; t < 8; t++) {
    int k = w * 8 + t;
    float r0 = (k < 32 && lane == k) ? 1.f : 0.f;
    float r1 = (k >= 32 && lane == k - 32) ? 1.f : 0.f;
    float i0 = 0.f, i1 = 0.f;
    { float c = cth[0], s = sth[0]; rx_loc(r0, i0, r1, i1, c, s);
      c = cth[1]; s = sth[1]; ry_loc(r0, i0, r1, i1, c, s); }
#pragma unroll
    for (int q = 1; q < 6; q++) {
      int L = 1 << (5 - q);
      float c = cth[q*3+0], s = sth[q*3+0]; rx_sh(r0, i0, r1, i1, c, s, L);
      c = cth[q*3+1]; s = sth[q*3+1]; ry_sh(r0, i0, r1, i1, c, s, L, lane);
    }
    r1 = __shfl_xor_sync(0xffffffffu, r1, 16);
    i1 = __shfl_xor_sync(0xffffffffu, i1, 16);
#pragma unroll
    for (int q = 1; q < 5; q++) {
      int Lc = 1 << (5 - q), Lt = 1 << (4 - q);
      float pr0 = __shfl_xor_sync(0xffffffffu, r0, Lt), pi0 = __shfl_xor_sync(0xffffffffu, i0, Lt);
      float pr1 = __shfl_xor_sync(0xffffffffu, r1, Lt), pi1 = __shfl_xor_sync(0xffffffffu, i1, Lt);
      if (lane & Lc) { r0 = pr0; i0 = pi0; r1 = pr1; i1 = pi1; }
    }
    { float c = cth[2], s = sth[2]; ry_loc(r0, i0, r1, i1, c, s); }
#pragma unroll
    for (int q = 1; q < 6; q++) {
      int L = 1 << (5 - q);
      float c = cth[q*3+2], s = sth[q*3+2]; ry_sh(r0, i0, r1, i1, c, s, L, lane);
    }
    Us[(2*lane)*64 + k] = r0;       Us[(2*lane+1)*64 + k] = i0;
    Us[(2*(lane+32))*64 + k] = r1;  Us[(2*(lane+32)+1)*64 + k] = i1;
  }
  __syncthreads();

#pragma unroll
  for (int i = 0; i < 8; i++)
    *(float4*)&g_Uri[b * 8192 + (tid + 256 * i) * 4] =
        *(const float4*)&Us[(tid + 256 * i) * 4];
  if (tid < 128) {
    float s = 0.f;
#pragma unroll
    for (int k = 0; k < 64; k++) s += Us[tid * 64 + k] * b1[k];
    g_bf[b * 128 + tid] = s;
  }
}

// ---------------------------------------------------------------------------
// Kernel 2: fold W1f tiles + W2 pack (68 blocks)
// ---------------------------------------------------------------------------
#define PREP_SZ 49152
__global__ __launch_bounds__(256) void k_fold(const float* __restrict__ w1,
                                              const float* __restrict__ w2) {
  int blk = blockIdx.x, tid = threadIdx.x;
  if (blk >= 64) {
    int base = (blk - 64) * 4096 + tid;
#pragma unroll
    for (int i = 0; i < 16; i++) {
      int idx = base + 256 * i;
      int c = idx >> 6, k = idx & 63;
      ushort_t h, l;
      split16(w2[idx], h, l);
      int fi = frag_idx(c, k, 4);
      g_A2h[fi] = h;
      g_A2l[fi] = l;
    }
    return;
  }
  extern __shared__ float pm[];
  float* Us = pm;            // 8192 floats
  float* Ws = pm + 8192;     // 4096 floats
  int b = blk >> 2, ch = blk & 3;

#pragma unroll
  for (int i = 0; i < 8; i++)
    *(float4*)&Us[(tid + 256 * i) * 4] =
        *(const float4*)&g_Uri[b * 8192 + (tid + 256 * i) * 4];
#pragma unroll
  for (int i = 0; i < 4; i++) {
    int idx = tid + 256 * i;
    int k = idx >> 4, c4 = (idx & 15) * 4;
    *(float4*)&Ws[k * 64 + c4] = *(const float4*)&w1[k * 256 + 64 * ch + c4];
  }
  __syncthreads();

  int rt = tid >> 4, ct = tid & 15;
  float acc[8][4];
#pragma unroll
  for (int u = 0; u < 8; u++)
#pragma unroll
    for (int v = 0; v < 4; v++) acc[u][v] = 0.f;
#pragma unroll 4
  for (int kk = 0; kk < 64; kk++) {
    float a[8], bb[4];
#pragma unroll
    for (int u = 0; u < 8; u++) a[u] = Us[(8 * rt + u) * 64 + kk];
#pragma unroll
    for (int v = 0; v < 4; v++) bb[v] = Ws[kk * 64 + ct + 16 * v];
#pragma unroll
    for (int u = 0; u < 8; u++)
#pragma unroll
      for (int v = 0; v < 4; v++) acc[u][v] = fmaf(a[u], bb[v], acc[u][v]);
  }
#pragma unroll
  for (int u = 0; u < 8; u++)
#pragma unroll
    for (int v = 0; v < 4; v++) {
      int r = 8 * rt + u, kcol = 64 * ch + ct + 16 * v;
      ushort_t h, l;
      split16(acc[u][v], h, l);
      int fi = frag_idx(r, kcol, 16);
      g_A1h[b][fi] = h;
      g_A1l[b][fi] = l;
    }
}

// ---------------------------------------------------------------------------
// Kernel 3: fused main (HMMA), 2D warp split to kill B-fragment replication.
// smem layout identical to R14.
// ---------------------------------------------------------------------------
#define XP      136
#define XPH_OFF 0
#define XPL_OFF 34816
#define Q_OFF   69632
#define BFS_OFF 104448
#define B2S_OFF 104960
#define SSUM_OFF 105984
#define SM_SZ   107008

__global__ __launch_bounds__(256, 2) void k_main(const float* __restrict__ x,
                                                 const float* __restrict__ b2,
                                                 float* __restrict__ out) {
  extern __shared__ unsigned char sm[];
  uint32_t* XpH = (uint32_t*)(sm + XPH_OFF);
  uint32_t* XpL = (uint32_t*)(sm + XPL_OFF);
  float*    S2  = (float*)sm;
  float*    Qf  = (float*)(sm + Q_OFF);
  uint32_t* Qu  = (uint32_t*)(sm + Q_OFF);
  float*    bfs = (float*)(sm + BFS_OFF);
  float*    b2s = (float*)(sm + B2S_OFF);
  float*    Ssum = (float*)(sm + SSUM_OFF);

  int tid = threadIdx.x;
  int w = tid >> 5, lane = tid & 31;
  int gID = lane >> 2, tig = lane & 3;
  int wm = w >> 1, wn = w & 1;
  int n0 = blockIdx.x * 128;
  int b = n0 >> 12, s0 = n0 & 4095;

  if (tid < 128) bfs[tid] = g_bf[b * 128 + tid];
  b2s[tid] = b2[tid];

  // ================= GEMM1: y = W1f @ x =================
  float C1[2][8][4];
#pragma unroll
  for (int mtl = 0; mtl < 2; mtl++)
#pragma unroll
    for (int ntl = 0; ntl < 8; ntl++)
#pragma unroll
      for (int e = 0; e < 4; e++) C1[mtl][ntl][e] = 0.f;

  const uint4* A1H4 = (const uint4*)g_A1h[b];
  const uint4* A1L4 = (const uint4*)g_A1l[b];

  int kq = tid >> 6;          // 0..3
  int p2 = (tid & 63) * 2;    // even position

  for (int ck = 0; ck < 2; ck++) {
    const float* xc = x + ((size_t)b * CCH + ck * 128) * HW + s0 + p2;
#pragma unroll
    for (int it = 0; it < 16; it++) {
      int kp = it * 4 + kq;
      float2 ev = *(const float2*)(xc + (size_t)(2 * kp) * HW);
      float2 ov = *(const float2*)(xc + (size_t)(2 * kp + 1) * HW);
      __half2 h0 = __floats2half2_rn(ev.x, ov.x);
      __half2 h1 = __floats2half2_rn(ev.y, ov.y);
      float l0a = ev.x - __low2float(h0), l0b = ov.x - __high2float(h0);
      float l1a = ev.y - __low2float(h1), l1b = ov.y - __high2float(h1);
      __half2 g0 = __floats2half2_rn(l0a, l0b);
      __half2 g1 = __floats2half2_rn(l1a, l1b);
      *(uint2*)&XpH[kp * XP + p2] = make_uint2(*(uint32_t*)&h0, *(uint32_t*)&h1);
      *(uint2*)&XpL[kp * XP + p2] = make_uint2(*(uint32_t*)&g0, *(uint32_t*)&g1);
    }
    __syncthreads();
#pragma unroll
    for (int ksl = 0; ksl < 8; ksl++) {
      int ksg = ck * 8 + ksl;
      uint4 ah0 = A1H4[((2 * wm) * 16 + ksg) * 32 + lane];
      uint4 ah1 = A1H4[((2 * wm + 1) * 16 + ksg) * 32 + lane];
      uint4 al0 = A1L4[((2 * wm) * 16 + ksg) * 32 + lane];
      uint4 al1 = A1L4[((2 * wm + 1) * 16 + ksg) * 32 + lane];
      int r0i = (ksl * 8 + tig) * XP + wn * 64 + gID;
      int r1i = (ksl * 8 + 4 + tig) * XP + wn * 64 + gID;
#pragma unroll
      for (int ntl = 0; ntl < 8; ntl++) {
        uint32_t bh0 = XpH[r0i + ntl * 8], bh1 = XpH[r1i + ntl * 8];
        uint32_t bl0 = XpL[r0i + ntl * 8], bl1 = XpL[r1i + ntl * 8];
        mma16816(C1[0][ntl], ah0.x, ah0.y, ah0.z, ah0.w, bh0, bh1);
        mma16816(C1[0][ntl], ah0.x, ah0.y, ah0.z, ah0.w, bl0, bl1);
        mma16816(C1[0][ntl], al0.x, al0.y, al0.z, al0.w, bh0, bh1);
        mma16816(C1[1][ntl], ah1.x, ah1.y, ah1.z, ah1.w, bh0, bh1);
        mma16816(C1[1][ntl], ah1.x, ah1.y, ah1.z, ah1.w, bl0, bl1);
        mma16816(C1[1][ntl], al1.x, al1.y, al1.z, al1.w, bh0, bh1);
      }
    }
    __syncthreads();
  }

  // ======== epilogue: bias, square, pair-sum -> Q[j][pos] ========
  {
#pragma unroll
    for (int mtl = 0; mtl < 2; mtl++) {
      int mtg = 2 * wm + mtl;
      float ba = bfs[mtg * 16 + gID];
      float bbv = bfs[mtg * 16 + gID + 8];
      int jA = mtg * 8 + (gID >> 1), jB = jA + 4;
#pragma unroll
      for (int ntl = 0; ntl < 8; ntl++) {
        float y0 = C1[mtl][ntl][0] + ba, y1 = C1[mtl][ntl][1] + ba;
        float y2 = C1[mtl][ntl][2] + bbv, y3 = C1[mtl][ntl][3] + bbv;
        float q0 = y0 * y0, q1 = y1 * y1, q2 = y2 * y2, q3 = y3 * y3;
        q0 += __shfl_xor_sync(0xffffffffu, q0, 4);
        q1 += __shfl_xor_sync(0xffffffffu, q1, 4);
        q2 += __shfl_xor_sync(0xffffffffu, q2, 4);
        q3 += __shfl_xor_sync(0xffffffffu, q3, 4);
        if (!(gID & 1)) {
          int pos = wn * 64 + ntl * 8 + tig * 2;
          *(float2*)&Qf[jA * XP + pos] = make_float2(q0, q1);
          *(float2*)&Qf[jB * XP + pos] = make_float2(q2, q3);
        }
      }
    }
  }
  __syncthreads();

  // ======== normalize: 2 threads per position ========
  {
    int half = tid >> 7, pos = tid & 127;
    float qv[32];
    float S = 0.f;
#pragma unroll
    for (int j = 0; j < 32; j++) {
      qv[j] = Qf[(32 * half + j) * XP + pos];
      S += qv[j];
    }
    Ssum[tid] = S;
    __syncthreads();
    float St = Ssum[pos] + Ssum[128 + pos];
    float inv = 1.0f / (sqrtf(St) + 1e-9f);
    float inv2 = inv * inv;
#pragma unroll
    for (int m = 0; m < 16; m++) {
      float p0 = qv[2 * m] * inv2;
      float p1 = qv[2 * m + 1] * inv2;
      __half2 hh = __floats2half2_rn(p0, p1);
      float l0 = p0 - __low2float(hh);
      float l1 = p1 - __high2float(hh);
      __half2 ll = __floats2half2_rn(l0, l1);
      int kpp = 16 * half + m;
      Qu[kpp * XP + pos] = *(uint32_t*)&hh;
      Qu[(32 + kpp) * XP + pos] = *(uint32_t*)&ll;
    }
  }
  __syncthreads();

  // ================= GEMM2: out = W2 @ probs =================
  const uint4* A2H4 = (const uint4*)g_A2h;
  const uint4* A2L4 = (const uint4*)g_A2l;
#pragma unroll 1
  for (int nh = 0; nh < 2; nh++) {
    float C2[4][4][4];
#pragma unroll
    for (int mtl = 0; mtl < 4; mtl++)
#pragma unroll
      for (int ntl = 0; ntl < 4; ntl++)
#pragma unroll
        for (int e = 0; e < 4; e++) C2[mtl][ntl][e] = 0.f;
#pragma unroll
    for (int ks = 0; ks < 4; ks++) {
      uint4 aH[4], aL[4];
#pragma unroll
      for (int mtl = 0; mtl < 4; mtl++) {
        int mtg = wm * 4 + mtl;
        aH[mtl] = A2H4[(mtg * 4 + ks) * 32 + lane];
        aL[mtl] = A2L4[(mtg * 4 + ks) * 32 + lane];
      }
      int rb0 = (ks * 8 + tig) * XP + nh * 64 + wn * 32 + gID;
      int rb1 = rb0 + 4 * XP;
#pragma unroll
      for (int ntl = 0; ntl < 4; ntl++) {
        uint32_t bh0 = Qu[rb0 + ntl * 8], bh1 = Qu[rb1 + ntl * 8];
        uint32_t bl0 = Qu[rb0 + 32 * XP + ntl * 8], bl1 = Qu[rb1 + 32 * XP + ntl * 8];
#pragma unroll
        for (int mtl = 0; mtl < 4; mtl++) {
          mma16816(C2[mtl][ntl], aH[mtl].x, aH[mtl].y, aH[mtl].z, aH[mtl].w, bh0, bh1);
          mma16816(C2[mtl][ntl], aH[mtl].x, aH[mtl].y, aH[mtl].z, aH[mtl].w, bl0, bl1);
          mma16816(C2[mtl][ntl], aL[mtl].x, aL[mtl].y, aL[mtl].z, aL[mtl].w, bh0, bh1);
        }
      }
    }
    // stage to S2 [256][66]
#pragma unroll
    for (int mtl = 0; mtl < 4; mtl++) {
      int c = (wm * 4 + mtl) * 16 + gID;
#pragma unroll
      for (int ntl = 0; ntl < 4; ntl++) {
        int pc = wn * 32 + ntl * 8 + tig * 2;
        S2[c * 66 + pc]       = C2[mtl][ntl][0];
        S2[c * 66 + pc + 1]   = C2[mtl][ntl][1];
        S2[(c + 8) * 66 + pc]     = C2[mtl][ntl][2];
        S2[(c + 8) * 66 + pc + 1] = C2[mtl][ntl][3];
      }
    }
    __syncthreads();
    {
      float bb2 = b2s[tid];
      float* ob = out + ((size_t)b * CCH + tid) * HW + s0 + nh * 64;
#pragma unroll
      for (int i = 0; i < 16; i++) {
        float2 u = *(float2*)&S2[tid * 66 + 4 * i];
        float2 v = *(float2*)&S2[tid * 66 + 4 * i + 2];
        float4 o = make_float4(u.x + bb2, u.y + bb2, v.x + bb2, v.y + bb2);
        *(float4*)(ob + 4 * i) = o;
      }
    }
    __syncthreads();
  }
}

// ---------------------------------------------------------------------------
extern "C" void kernel_launch(void* const* d_in, const int* in_sizes, int n_in,
                              void* d_out, int out_size) {
  const float* x     = (const float*)d_in[0];
  const float* style = (const float*)d_in[1];
  const float* w1    = (const float*)d_in[2];
  const float* b1    = (const float*)d_in[3];
  const float* smw   = (const float*)d_in[4];
  const float* smb   = (const float*)d_in[5];
  const float* wts   = (const float*)d_in[6];
  const float* w2    = (const float*)d_in[7];
  const float* b2    = (const float*)d_in[8];
  float* out = (float*)d_out;

  cudaFuncSetAttribute(k_fold, cudaFuncAttributeMaxDynamicSharedMemorySize, PREP_SZ);
  cudaFuncSetAttribute(k_main, cudaFuncAttributeMaxDynamicSharedMemorySize, SM_SZ);

  k_u<<<BATCH, 256>>>(style, smw, smb, wts, b1);
  k_fold<<<68, 256, PREP_SZ>>>(w1, w2);
  k_main<<<NPOS / 128, 256, SM_SZ>>>(x, b2, out);
}

// round 17
// speedup vs baseline: 1.0458x; 1.0458x over previous
#include <cuda_runtime.h>
#include <cuda_fp16.h>
#include <math.h>
#include <stdint.h>

#define BATCH 16
#define CCH   256
#define HW    4096
#define NPOS  (BATCH*HW)
#define QDIM  64
#define SD    512
#define NANG  18

typedef unsigned short ushort_t;

// ---------------- scratch globals ----------------
__device__ float g_Uri[BATCH * 8192];            // rows 2a=Re, 2a+1=Im of U
__device__ float g_bf[BATCH * 128];              // Ũ @ b1
__device__ __align__(16) ushort_t g_A1h[BATCH][32768];
__device__ __align__(16) ushort_t g_A1l[BATCH][32768];
__device__ __align__(16) ushort_t g_A2h[16384];
__device__ __align__(16) ushort_t g_A2l[16384];

// ---------------- mma helper ----------------
__device__ __forceinline__ void mma16816(float* c, uint32_t a0, uint32_t a1,
                                         uint32_t a2, uint32_t a3,
                                         uint32_t b0, uint32_t b1) {
  asm volatile(
      "mma.sync.aligned.m16n8k16.row.col.f32.f16.f16.f32 "
      "{%0,%1,%2,%3}, {%4,%5,%6,%7}, {%8,%9}, {%0,%1,%2,%3};"
      : "+f"(c[0]), "+f"(c[1]), "+f"(c[2]), "+f"(c[3])
      : "r"(a0), "r"(a1), "r"(a2), "r"(a3), "r"(b0), "r"(b1));
}

__device__ __forceinline__ void split16(float v, ushort_t& h, ushort_t& l) {
  __half hh = __float2half_rn(v);
  float lo = v - __half2float(hh);
  h = __half_as_ushort(hh);
  l = __half_as_ushort(__float2half_rn(lo));
}

// fragment-linear ushort index for A operand (m16n8k16 row-major A)
__device__ __forceinline__ int frag_idx(int r, int k, int KS) {
  int mt = r >> 4, rr = r & 15;
  int gID = rr & 7, sm = rr >> 3;
  int ks = k >> 4, kin = k & 15;
  int sk = kin >> 3, tg = (kin & 7) >> 1, hf = kin & 1;
  return (((mt * KS + ks) * 32 + gID * 4 + tg) * 4 + (sm + 2 * sk)) * 2 + hf;
}

// ---------------- circuit helpers ----------------
__device__ __forceinline__ void rx_sh(float& r0, float& i0, float& r1, float& i1,
                                      float c, float s, int L) {
  float pr0 = __shfl_xor_sync(0xffffffffu, r0, L), pi0 = __shfl_xor_sync(0xffffffffu, i0, L);
  float pr1 = __shfl_xor_sync(0xffffffffu, r1, L), pi1 = __shfl_xor_sync(0xffffffffu, i1, L);
  r0 = fmaf(s, pi0, c * r0);  i0 = fmaf(-s, pr0, c * i0);
  r1 = fmaf(s, pi1, c * r1);  i1 = fmaf(-s, pr1, c * i1);
}
__device__ __forceinline__ void rx_loc(float& r0, float& i0, float& r1, float& i1,
                                       float c, float s) {
  float nr0 = fmaf(s, i1, c * r0), ni0 = fmaf(-s, r1, c * i0);
  float nr1 = fmaf(s, i0, c * r1), ni1 = fmaf(-s, r0, c * i1);
  r0 = nr0; i0 = ni0; r1 = nr1; i1 = ni1;
}
__device__ __forceinline__ void ry_sh(float& r0, float& i0, float& r1, float& i1,
                                      float c, float s, int L, int lane) {
  float t = (lane & L) ? s : -s;
  float pr0 = __shfl_xor_sync(0xffffffffu, r0, L), pi0 = __shfl_xor_sync(0xffffffffu, i0, L);
  float pr1 = __shfl_xor_sync(0xffffffffu, r1, L), pi1 = __shfl_xor_sync(0xffffffffu, i1, L);
  r0 = fmaf(t, pr0, c * r0);  i0 = fmaf(t, pi0, c * i0);
  r1 = fmaf(t, pr1, c * r1);  i1 = fmaf(t, pi1, c * i1);
}
__device__ __forceinline__ void ry_loc(float& r0, float& i0, float& r1, float& i1,
                                       float c, float s) {
  float nr0 = fmaf(-s, r1, c * r0), ni0 = fmaf(-s, i1, c * i0);
  float nr1 = fmaf(s, r0, c * r1),  ni1 = fmaf(s, i0, c * i1);
  r0 = nr0; i0 = ni0; r1 = nr1; i1 = ni1;
}

// ---------------------------------------------------------------------------
// Kernel 1: angles + build U (64 blocks: 4 basis slices x 16 batches).
// Each warp pushes only TWO basis vectors serially (dependency chain / 4).
// ---------------------------------------------------------------------------
__global__ __launch_bounds__(256) void k_u(
    const float* __restrict__ style, const float* __restrict__ smw,
    const float* __restrict__ smb, const float* __restrict__ wts) {
  __shared__ float cth[NANG], sth[NANG];
  int blk = blockIdx.x, tid = threadIdx.x;
  int b = blk >> 2, slice = blk & 3;
  int w = tid >> 5, lane = tid & 31;

  for (int o = w; o < NANG; o += 8) {
    float p = 0.f;
#pragma unroll
    for (int j = 0; j < 16; j++)
      p += smw[o * SD + lane + 32 * j] * style[b * SD + lane + 32 * j];
#pragma unroll
    for (int off = 16; off > 0; off >>= 1) p += __shfl_xor_sync(0xffffffffu, p, off);
    if (lane == 0) {
      float tp = wts[o] + smb[o] + p;
      cth[o] = cosf(0.5f * tp);
      sth[o] = sinf(0.5f * tp);
    }
  }
  __syncthreads();

  float* U = g_Uri + b * 8192;
#pragma unroll
  for (int t = 0; t < 2; t++) {
    int k = slice * 16 + w * 2 + t;
    float r0 = (k < 32 && lane == k) ? 1.f : 0.f;
    float r1 = (k >= 32 && lane == k - 32) ? 1.f : 0.f;
    float i0 = 0.f, i1 = 0.f;
    { float c = cth[0], s = sth[0]; rx_loc(r0, i0, r1, i1, c, s);
      c = cth[1]; s = sth[1]; ry_loc(r0, i0, r1, i1, c, s); }
#pragma unroll
    for (int q = 1; q < 6; q++) {
      int L = 1 << (5 - q);
      float c = cth[q*3+0], s = sth[q*3+0]; rx_sh(r0, i0, r1, i1, c, s, L);
      c = cth[q*3+1]; s = sth[q*3+1]; ry_sh(r0, i0, r1, i1, c, s, L, lane);
    }
    r1 = __shfl_xor_sync(0xffffffffu, r1, 16);
    i1 = __shfl_xor_sync(0xffffffffu, i1, 16);
#pragma unroll
    for (int q = 1; q < 5; q++) {
      int Lc = 1 << (5 - q), Lt = 1 << (4 - q);
      float pr0 = __shfl_xor_sync(0xffffffffu, r0, Lt), pi0 = __shfl_xor_sync(0xffffffffu, i0, Lt);
      float pr1 = __shfl_xor_sync(0xffffffffu, r1, Lt), pi1 = __shfl_xor_sync(0xffffffffu, i1, Lt);
      if (lane & Lc) { r0 = pr0; i0 = pi0; r1 = pr1; i1 = pi1; }
    }
    { float c = cth[2], s = sth[2]; ry_loc(r0, i0, r1, i1, c, s); }
#pragma unroll
    for (int q = 1; q < 6; q++) {
      int L = 1 << (5 - q);
      float c = cth[q*3+2], s = sth[q*3+2]; ry_sh(r0, i0, r1, i1, c, s, L, lane);
    }
    U[(2*lane)*64 + k] = r0;       U[(2*lane+1)*64 + k] = i0;
    U[(2*(lane+32))*64 + k] = r1;  U[(2*(lane+32)+1)*64 + k] = i1;
  }
}

// ---------------------------------------------------------------------------
// Kernel 2: fold W1f tiles + bias (ch==0) + W2 pack (68 blocks)
// ---------------------------------------------------------------------------
#define PREP_SZ 49152
__global__ __launch_bounds__(256) void k_fold(const float* __restrict__ w1,
                                              const float* __restrict__ b1,
                                              const float* __restrict__ w2) {
  int blk = blockIdx.x, tid = threadIdx.x;
  if (blk >= 64) {
    int base = (blk - 64) * 4096 + tid;
#pragma unroll
    for (int i = 0; i < 16; i++) {
      int idx = base + 256 * i;
      int c = idx >> 6, k = idx & 63;
      ushort_t h, l;
      split16(w2[idx], h, l);
      int fi = frag_idx(c, k, 4);
      g_A2h[fi] = h;
      g_A2l[fi] = l;
    }
    return;
  }
  extern __shared__ float pm[];
  float* Us = pm;            // 8192 floats
  float* Ws = pm + 8192;     // 4096 floats
  int b = blk >> 2, ch = blk & 3;

#pragma unroll
  for (int i = 0; i < 8; i++)
    *(float4*)&Us[(tid + 256 * i) * 4] =
        *(const float4*)&g_Uri[b * 8192 + (tid + 256 * i) * 4];
#pragma unroll
  for (int i = 0; i < 4; i++) {
    int idx = tid + 256 * i;
    int k = idx >> 4, c4 = (idx & 15) * 4;
    *(float4*)&Ws[k * 64 + c4] = *(const float4*)&w1[k * 256 + 64 * ch + c4];
  }
  __syncthreads();

  int rt = tid >> 4, ct = tid & 15;
  float acc[8][4];
#pragma unroll
  for (int u = 0; u < 8; u++)
#pragma unroll
    for (int v = 0; v < 4; v++) acc[u][v] = 0.f;
#pragma unroll 4
  for (int kk = 0; kk < 64; kk++) {
    float a[8], bb[4];
#pragma unroll
    for (int u = 0; u < 8; u++) a[u] = Us[(8 * rt + u) * 64 + kk];
#pragma unroll
    for (int v = 0; v < 4; v++) bb[v] = Ws[kk * 64 + ct + 16 * v];
#pragma unroll
    for (int u = 0; u < 8; u++)
#pragma unroll
      for (int v = 0; v < 4; v++) acc[u][v] = fmaf(a[u], bb[v], acc[u][v]);
  }
#pragma unroll
  for (int u = 0; u < 8; u++)
#pragma unroll
    for (int v = 0; v < 4; v++) {
      int r = 8 * rt + u, kcol = 64 * ch + ct + 16 * v;
      ushort_t h, l;
      split16(acc[u][v], h, l);
      int fi = frag_idx(r, kcol, 16);
      g_A1h[b][fi] = h;
      g_A1l[b][fi] = l;
    }
  if (ch == 0 && tid < 128) {
    float s = 0.f;
#pragma unroll
    for (int k = 0; k < 64; k++) s += Us[tid * 64 + k] * b1[k];
    g_bf[b * 128 + tid] = s;
  }
}

// ---------------------------------------------------------------------------
// Kernel 3: fused main (HMMA) — identical to R16.
// ---------------------------------------------------------------------------
#define XP      136
#define XPH_OFF 0
#define XPL_OFF 34816
#define Q_OFF   69632
#define BFS_OFF 104448
#define B2S_OFF 104960
#define SSUM_OFF 105984
#define SM_SZ   107008

__global__ __launch_bounds__(256, 2) void k_main(const float* __restrict__ x,
                                                 const float* __restrict__ b2,
                                                 float* __restrict__ out) {
  extern __shared__ unsigned char sm[];
  uint32_t* XpH = (uint32_t*)(sm + XPH_OFF);
  uint32_t* XpL = (uint32_t*)(sm + XPL_OFF);
  float*    S2  = (float*)sm;
  float*    Qf  = (float*)(sm + Q_OFF);
  uint32_t* Qu  = (uint32_t*)(sm + Q_OFF);
  float*    bfs = (float*)(sm + BFS_OFF);
  float*    b2s = (float*)(sm + B2S_OFF);
  float*    Ssum = (float*)(sm + SSUM_OFF);

  int tid = threadIdx.x;
  int w = tid >> 5, lane = tid & 31;
  int gID = lane >> 2, tig = lane & 3;
  int wm = w >> 1, wn = w & 1;
  int n0 = blockIdx.x * 128;
  int b = n0 >> 12, s0 = n0 & 4095;

  if (tid < 128) bfs[tid] = g_bf[b * 128 + tid];
  b2s[tid] = b2[tid];

  // ================= GEMM1: y = W1f @ x =================
  float C1[2][8][4];
#pragma unroll
  for (int mtl = 0; mtl < 2; mtl++)
#pragma unroll
    for (int ntl = 0; ntl < 8; ntl++)
#pragma unroll
      for (int e = 0; e < 4; e++) C1[mtl][ntl][e] = 0.f;

  const uint4* A1H4 = (const uint4*)g_A1h[b];
  const uint4* A1L4 = (const uint4*)g_A1l[b];

  int kq = tid >> 6;
  int p2 = (tid & 63) * 2;

  for (int ck = 0; ck < 2; ck++) {
    const float* xc = x + ((size_t)b * CCH + ck * 128) * HW + s0 + p2;
#pragma unroll
    for (int it = 0; it < 16; it++) {
      int kp = it * 4 + kq;
      float2 ev = *(const float2*)(xc + (size_t)(2 * kp) * HW);
      float2 ov = *(const float2*)(xc + (size_t)(2 * kp + 1) * HW);
      __half2 h0 = __floats2half2_rn(ev.x, ov.x);
      __half2 h1 = __floats2half2_rn(ev.y, ov.y);
      float l0a = ev.x - __low2float(h0), l0b = ov.x - __high2float(h0);
      float l1a = ev.y - __low2float(h1), l1b = ov.y - __high2float(h1);
      __half2 g0 = __floats2half2_rn(l0a, l0b);
      __half2 g1 = __floats2half2_rn(l1a, l1b);
      *(uint2*)&XpH[kp * XP + p2] = make_uint2(*(uint32_t*)&h0, *(uint32_t*)&h1);
      *(uint2*)&XpL[kp * XP + p2] = make_uint2(*(uint32_t*)&g0, *(uint32_t*)&g1);
    }
    __syncthreads();
#pragma unroll
    for (int ksl = 0; ksl < 8; ksl++) {
      int ksg = ck * 8 + ksl;
      uint4 ah0 = A1H4[((2 * wm) * 16 + ksg) * 32 + lane];
      uint4 ah1 = A1H4[((2 * wm + 1) * 16 + ksg) * 32 + lane];
      uint4 al0 = A1L4[((2 * wm) * 16 + ksg) * 32 + lane];
      uint4 al1 = A1L4[((2 * wm + 1) * 16 + ksg) * 32 + lane];
      int r0i = (ksl * 8 + tig) * XP + wn * 64 + gID;
      int r1i = (ksl * 8 + 4 + tig) * XP + wn * 64 + gID;
#pragma unroll
      for (int ntl = 0; ntl < 8; ntl++) {
        uint32_t bh0 = XpH[r0i + ntl * 8], bh1 = XpH[r1i + ntl * 8];
        uint32_t bl0 = XpL[r0i + ntl * 8], bl1 = XpL[r1i + ntl * 8];
        mma16816(C1[0][ntl], ah0.x, ah0.y, ah0.z, ah0.w, bh0, bh1);
        mma16816(C1[0][ntl], ah0.x, ah0.y, ah0.z, ah0.w, bl0, bl1);
        mma16816(C1[0][ntl], al0.x, al0.y, al0.z, al0.w, bh0, bh1);
        mma16816(C1[1][ntl], ah1.x, ah1.y, ah1.z, ah1.w, bh0, bh1);
        mma16816(C1[1][ntl], ah1.x, ah1.y, ah1.z, ah1.w, bl0, bl1);
        mma16816(C1[1][ntl], al1.x, al1.y, al1.z, al1.w, bh0, bh1);
      }
    }
    __syncthreads();
  }

  // ======== epilogue: bias, square, pair-sum -> Q[j][pos] ========
  {
#pragma unroll
    for (int mtl = 0; mtl < 2; mtl++) {
      int mtg = 2 * wm + mtl;
      float ba = bfs[mtg * 16 + gID];
      float bbv = bfs[mtg * 16 + gID + 8];
      int jA = mtg * 8 + (gID >> 1), jB = jA + 4;
#pragma unroll
      for (int ntl = 0; ntl < 8; ntl++) {
        float y0 = C1[mtl][ntl][0] + ba, y1 = C1[mtl][ntl][1] + ba;
        float y2 = C1[mtl][ntl][2] + bbv, y3 = C1[mtl][ntl][3] + bbv;
        float q0 = y0 * y0, q1 = y1 * y1, q2 = y2 * y2, q3 = y3 * y3;
        q0 += __shfl_xor_sync(0xffffffffu, q0, 4);
        q1 += __shfl_xor_sync(0xffffffffu, q1, 4);
        q2 += __shfl_xor_sync(0xffffffffu, q2, 4);
        q3 += __shfl_xor_sync(0xffffffffu, q3, 4);
        if (!(gID & 1)) {
          int pos = wn * 64 + ntl * 8 + tig * 2;
          *(float2*)&Qf[jA * XP + pos] = make_float2(q0, q1);
          *(float2*)&Qf[jB * XP + pos] = make_float2(q2, q3);
        }
      }
    }
  }
  __syncthreads();

  // ======== normalize: 2 threads per position ========
  {
    int half = tid >> 7, pos = tid & 127;
    float qv[32];
    float S = 0.f;
#pragma unroll
    for (int j = 0; j < 32; j++) {
      qv[j] = Qf[(32 * half + j) * XP + pos];
      S += qv[j];
    }
    Ssum[tid] = S;
    __syncthreads();
    float St = Ssum[pos] + Ssum[128 + pos];
    float inv = 1.0f / (sqrtf(St) + 1e-9f);
    float inv2 = inv * inv;
#pragma unroll
    for (int m = 0; m < 16; m++) {
      float p0 = qv[2 * m] * inv2;
      float p1 = qv[2 * m + 1] * inv2;
      __half2 hh = __floats2half2_rn(p0, p1);
      float l0 = p0 - __low2float(hh);
      float l1 = p1 - __high2float(hh);
      __half2 ll = __floats2half2_rn(l0, l1);
      int kpp = 16 * half + m;
      Qu[kpp * XP + pos] = *(uint32_t*)&hh;
      Qu[(32 + kpp) * XP + pos] = *(uint32_t*)&ll;
    }
  }
  __syncthreads();

  // ================= GEMM2: out = W2 @ probs =================
  const uint4* A2H4 = (const uint4*)g_A2h;
  const uint4* A2L4 = (const uint4*)g_A2l;
#pragma unroll 1
  for (int nh = 0; nh < 2; nh++) {
    float C2[4][4][4];
#pragma unroll
    for (int mtl = 0; mtl < 4; mtl++)
#pragma unroll
      for (int ntl = 0; ntl < 4; ntl++)
#pragma unroll
        for (int e = 0; e < 4; e++) C2[mtl][ntl][e] = 0.f;
#pragma unroll
    for (int ks = 0; ks < 4; ks++) {
      uint4 aH[4], aL[4];
#pragma unroll
      for (int mtl = 0; mtl < 4; mtl++) {
        int mtg = wm * 4 + mtl;
        aH[mtl] = A2H4[(mtg * 4 + ks) * 32 + lane];
        aL[mtl] = A2L4[(mtg * 4 + ks) * 32 + lane];
      }
      int rb0 = (ks * 8 + tig) * XP + nh * 64 + wn * 32 + gID;
      int rb1 = rb0 + 4 * XP;
#pragma unroll
      for (int ntl = 0; ntl < 4; ntl++) {
        uint32_t bh0 = Qu[rb0 + ntl * 8], bh1 = Qu[rb1 + ntl * 8];
        uint32_t bl0 = Qu[rb0 + 32 * XP + ntl * 8], bl1 = Qu[rb1 + 32 * XP + ntl * 8];
#pragma unroll
        for (int mtl = 0; mtl < 4; mtl++) {
          mma16816(C2[mtl][ntl], aH[mtl].x, aH[mtl].y, aH[mtl].z, aH[mtl].w, bh0, bh1);
          mma16816(C2[mtl][ntl], aH[mtl].x, aH[mtl].y, aH[mtl].z, aH[mtl].w, bl0, bl1);
          mma16816(C2[mtl][ntl], aL[mtl].x, aL[mtl].y, aL[mtl].z, aL[mtl].w, bh0, bh1);
        }
      }
    }
#pragma unroll
    for (int mtl = 0; mtl < 4; mtl++) {
      int c = (wm * 4 + mtl) * 16 + gID;
#pragma unroll
      for (int ntl = 0; ntl < 4; ntl++) {
        int pc = wn * 32 + ntl * 8 + tig * 2;
        S2[c * 66 + pc]       = C2[mtl][ntl][0];
        S2[c * 66 + pc + 1]   = C2[mtl][ntl][1];
        S2[(c + 8) * 66 + pc]     = C2[mtl][ntl][2];
        S2[(c + 8) * 66 + pc + 1] = C2[mtl][ntl][3];
      }
    }
    __syncthreads();
    {
      float bb2 = b2s[tid];
      float* ob = out + ((size_t)b * CCH + tid) * HW + s0 + nh * 64;
#pragma unroll
      for (int i = 0; i < 16; i++) {
        float2 u = *(float2*)&S2[tid * 66 + 4 * i];
        float2 v = *(float2*)&S2[tid * 66 + 4 * i + 2];
        float4 o = make_float4(u.x + bb2, u.y + bb2, v.x + bb2, v.y + bb2);
        *(float4*)(ob + 4 * i) = o;
      }
    }
    __syncthreads();
  }
}

// ---------------------------------------------------------------------------
extern "C" void kernel_launch(void* const* d_in, const int* in_sizes, int n_in,
                              void* d_out, int out_size) {
  const float* x     = (const float*)d_in[0];
  const float* style = (const float*)d_in[1];
  const float* w1    = (const float*)d_in[2];
  const float* b1    = (const float*)d_in[3];
  const float* smw   = (const float*)d_in[4];
  const float* smb   = (const float*)d_in[5];
  const float* wts   = (const float*)d_in[6];
  const float* w2    = (const float*)d_in[7];
  const float* b2    = (const float*)d_in[8];
  float* out = (float*)d_out;

  cudaFuncSetAttribute(k_fold, cudaFuncAttributeMaxDynamicSharedMemorySize, PREP_SZ);
  cudaFuncSetAttribute(k_main, cudaFuncAttributeMaxDynamicSharedMemorySize, SM_SZ);

  k_u<<<64, 256>>>(style, smw, smb, wts);
  k_fold<<<68, 256, PREP_SZ>>>(w1, b1, w2);
  k_main<<<NPOS / 128, 256, SM_SZ>>>(x, b2, out);
}